// round 1
// baseline (speedup 1.0000x reference)
#include <cuda_runtime.h>
#include <cuda_bf16.h>

// Problem constants
#define B_ 8
#define C_ 256
#define H_ 25
#define W_ 25
#define N_ 256
#define OUT_ 7
#define NBIN 49
#define SP_ 4
#define IN_ 12544   // C*7*7
#define DFC_ 1024
#define FCC_ 512
#define SS_ (25.0f/255.0f)
#define TRANS_STD_ 0.1f

// Scratch (device globals — no allocation allowed)
__device__ float g_xt[B_*H_*W_*C_];    // (B,H,W,C)
__device__ float g_p0[N_*IN_];
__device__ float g_h1[N_*DFC_];
__device__ float g_h2[N_*DFC_];
__device__ float g_off[N_*2*NBIN];
__device__ float g_p1[N_*IN_];
__device__ float g_f1[N_*FCC_];
__device__ float g_f2[N_*FCC_];

// ---------------------------------------------------------------------------
// Transpose x (B,C,H,W) -> xt (B,H*W,C)
// ---------------------------------------------------------------------------
__global__ void transpose_kernel(const float* __restrict__ x, float* __restrict__ xt) {
    __shared__ float tile[32][33];
    int b  = blockIdx.z;
    int s0 = blockIdx.x * 32;   // spatial (h*W+w)
    int c0 = blockIdx.y * 32;   // channel
    int tx = threadIdx.x, ty = threadIdx.y; // 32 x 8
    const int HW = H_*W_;
    #pragma unroll
    for (int i = ty; i < 32; i += 8) {
        int c = c0 + i, s = s0 + tx;
        if (c < C_ && s < HW) tile[i][tx] = x[(b*C_ + c)*HW + s];
    }
    __syncthreads();
    #pragma unroll
    for (int i = ty; i < 32; i += 8) {
        int s = s0 + i, c = c0 + tx;
        if (s < HW && c < C_) xt[(b*HW + s)*C_ + c] = tile[tx][i];
    }
}

// ---------------------------------------------------------------------------
// Deformable ROI pool: one block per ROI, 256 threads (= channels),
// loop over the 49 bins. off may be nullptr (zero offsets).
// Output layout: out[n][c*49 + bin]  (matches reference reshape(N,-1))
// ---------------------------------------------------------------------------
__global__ void pool_kernel(const float* __restrict__ xt,
                            const float* __restrict__ rois,
                            const float* __restrict__ off,
                            float* __restrict__ out) {
    int n = blockIdx.x;
    int t = threadIdx.x;   // channel

    const float* r = rois + n*5;
    int   b  = (int)r[0];
    float sw = rintf(r[1])*SS_ - 0.5f;
    float sh = rintf(r[2])*SS_ - 0.5f;
    float rw = fmaxf((rintf(r[3]) + 1.0f)*SS_ - 0.5f - sw, 0.1f);
    float rh = fmaxf((rintf(r[4]) + 1.0f)*SS_ - 0.5f - sh, 0.1f);
    float bw = rw / (float)OUT_;
    float bh = rh / (float)OUT_;

    __shared__ float s_w00[16], s_w01[16], s_w10[16], s_w11[16], s_vs[16];
    __shared__ int   s_i00[16], s_i01[16], s_i10[16], s_i11[16];

    const int base_b = b * (H_*W_) * C_;

    for (int bin = 0; bin < NBIN; bin++) {
        int ph = bin / OUT_, pw = bin % OUT_;
        if (t < 16) {
            float txo = off ? off[n*(2*NBIN) + bin]        * TRANS_STD_ : 0.0f;
            float tyo = off ? off[n*(2*NBIN) + NBIN + bin] * TRANS_STD_ : 0.0f;
            float wstart = pw*bw + sw + txo*rw;
            float hstart = ph*bh + sh + tyo*rh;
            int i = t >> 2;   // y sample
            int j = t & 3;    // x sample
            float sx = wstart + (float)j * (bw * 0.25f);
            float sy = hstart + (float)i * (bh * 0.25f);
            bool valid = (sx >= -0.5f) && (sx <= (float)W_ - 0.5f) &&
                         (sy >= -0.5f) && (sy <= (float)H_ - 0.5f);
            float xc = fminf(fmaxf(sx, 0.0f), (float)(W_-1));
            float yc = fminf(fmaxf(sy, 0.0f), (float)(H_-1));
            float x0 = floorf(xc), y0 = floorf(yc);
            float dx = xc - x0,  dy = yc - y0;
            int xi0 = (int)x0, yi0 = (int)y0;
            int xi1 = (int)ceilf(xc), yi1 = (int)ceilf(yc);
            float vm = valid ? 1.0f : 0.0f;
            s_w00[t] = vm*(1.0f-dx)*(1.0f-dy);
            s_w01[t] = vm*dx*(1.0f-dy);
            s_w10[t] = vm*(1.0f-dx)*dy;
            s_w11[t] = vm*dx*dy;
            s_vs[t]  = vm;
            s_i00[t] = base_b + (yi0*W_ + xi0)*C_;
            s_i01[t] = base_b + (yi0*W_ + xi1)*C_;
            s_i10[t] = base_b + (yi1*W_ + xi0)*C_;
            s_i11[t] = base_b + (yi1*W_ + xi1)*C_;
        }
        __syncthreads();

        float cnt = 0.0f;
        #pragma unroll
        for (int q = 0; q < 16; q++) cnt += s_vs[q];
        float inv = 1.0f / fmaxf(cnt, 1.0f);

        float acc = 0.0f;
        #pragma unroll
        for (int q = 0; q < 16; q++) {
            acc += s_w00[q]*xt[s_i00[q] + t];
            acc += s_w01[q]*xt[s_i01[q] + t];
            acc += s_w10[q]*xt[s_i10[q] + t];
            acc += s_w11[q]*xt[s_i11[q] + t];
        }
        out[n*IN_ + t*NBIN + bin] = acc * inv;
        __syncthreads();
    }
}

// ---------------------------------------------------------------------------
// SGEMM: C[n][m] = act( sum_k A[n][k]*W[m][k] + bias[m] )
// BM=32, BN=64, BK=16, 256 threads, TM=2 x TN=4.
// Requires: Nrows %32==0, M %64==0, K %16==0 (true for all uses).
// ---------------------------------------------------------------------------
__global__ void gemm_kernel(const float* __restrict__ A,
                            const float* __restrict__ Wm,
                            const float* __restrict__ bias,
                            float* __restrict__ C,
                            int M, int K, int relu) {
    __shared__ float As[32][17];
    __shared__ float Ws[64][17];

    int tid = threadIdx.x;
    int tx = tid & 15;        // 0..15 -> col group
    int ty = tid >> 4;        // 0..15 -> row group
    int n0 = blockIdx.y * 32;
    int m0 = blockIdx.x * 64;

    float acc[2][4];
    #pragma unroll
    for (int i = 0; i < 2; i++)
        #pragma unroll
        for (int j = 0; j < 4; j++) acc[i][j] = 0.0f;

    int lk = tid & 15;        // k within tile
    int lr = tid >> 4;        // row base for loads

    for (int k0 = 0; k0 < K; k0 += 16) {
        As[lr     ][lk] = A[(n0 + lr     )*K + k0 + lk];
        As[lr + 16][lk] = A[(n0 + lr + 16)*K + k0 + lk];
        #pragma unroll
        for (int p = 0; p < 4; p++)
            Ws[lr + 16*p][lk] = Wm[(m0 + lr + 16*p)*K + k0 + lk];
        __syncthreads();

        #pragma unroll
        for (int kk = 0; kk < 16; kk++) {
            float a0 = As[ty*2    ][kk];
            float a1 = As[ty*2 + 1][kk];
            float b0 = Ws[tx*4    ][kk];
            float b1 = Ws[tx*4 + 1][kk];
            float b2 = Ws[tx*4 + 2][kk];
            float b3 = Ws[tx*4 + 3][kk];
            acc[0][0] += a0*b0; acc[0][1] += a0*b1; acc[0][2] += a0*b2; acc[0][3] += a0*b3;
            acc[1][0] += a1*b0; acc[1][1] += a1*b1; acc[1][2] += a1*b2; acc[1][3] += a1*b3;
        }
        __syncthreads();
    }

    #pragma unroll
    for (int i = 0; i < 2; i++) {
        int row = n0 + ty*2 + i;
        #pragma unroll
        for (int j = 0; j < 4; j++) {
            int col = m0 + tx*4 + j;
            float v = acc[i][j] + bias[col];
            if (relu) v = fmaxf(v, 0.0f);
            C[row*M + col] = v;
        }
    }
}

// ---------------------------------------------------------------------------
// off3: out[n][o] = h[n] . w3[o] + b3[o]   (98 outputs, K=1024)
// ---------------------------------------------------------------------------
__global__ void off3_kernel(const float* __restrict__ h,
                            const float* __restrict__ w3,
                            const float* __restrict__ b3,
                            float* __restrict__ out) {
    int n = blockIdx.x;
    __shared__ float sh[DFC_];
    for (int k = threadIdx.x; k < DFC_; k += blockDim.x) sh[k] = h[n*DFC_ + k];
    __syncthreads();
    for (int o = threadIdx.x; o < 2*NBIN; o += blockDim.x) {
        const float* w = w3 + o*DFC_;
        float acc = b3[o];
        #pragma unroll 4
        for (int k = 0; k < DFC_; k++) acc += sh[k]*w[k];
        out[n*(2*NBIN) + o] = acc;
    }
}

// ---------------------------------------------------------------------------
// box: out[n][w] = f2[n] . box_w[w] + box_b[w]   (4 outputs, K=512)
// ---------------------------------------------------------------------------
__global__ void box_kernel(const float* __restrict__ f2,
                           const float* __restrict__ bw,
                           const float* __restrict__ bb,
                           float* __restrict__ out) {
    int n = blockIdx.x;
    int w = threadIdx.x >> 5;
    int lane = threadIdx.x & 31;
    float acc = 0.0f;
    for (int k = lane; k < FCC_; k += 32) acc += f2[n*FCC_ + k]*bw[w*FCC_ + k];
    #pragma unroll
    for (int o = 16; o > 0; o >>= 1) acc += __shfl_down_sync(0xffffffffu, acc, o);
    if (lane == 0) out[n*4 + w] = acc + bb[w];
}

// ---------------------------------------------------------------------------
extern "C" void kernel_launch(void* const* d_in, const int* in_sizes, int n_in,
                              void* d_out, int out_size) {
    const float* x      = (const float*)d_in[0];
    const float* rois   = (const float*)d_in[1];
    const float* off_w1 = (const float*)d_in[2];
    const float* off_b1 = (const float*)d_in[3];
    const float* off_w2 = (const float*)d_in[4];
    const float* off_b2 = (const float*)d_in[5];
    const float* off_w3 = (const float*)d_in[6];
    const float* off_b3 = (const float*)d_in[7];
    const float* fc1_w  = (const float*)d_in[8];
    const float* fc1_b  = (const float*)d_in[9];
    const float* fc2_w  = (const float*)d_in[10];
    const float* fc2_b  = (const float*)d_in[11];
    const float* box_w  = (const float*)d_in[12];
    const float* box_b  = (const float*)d_in[13];
    float* out = (float*)d_out;

    float *xt, *p0, *h1, *h2, *offb, *p1, *f1, *f2;
    cudaGetSymbolAddress((void**)&xt,   g_xt);
    cudaGetSymbolAddress((void**)&p0,   g_p0);
    cudaGetSymbolAddress((void**)&h1,   g_h1);
    cudaGetSymbolAddress((void**)&h2,   g_h2);
    cudaGetSymbolAddress((void**)&offb, g_off);
    cudaGetSymbolAddress((void**)&p1,   g_p1);
    cudaGetSymbolAddress((void**)&f1,   g_f1);
    cudaGetSymbolAddress((void**)&f2,   g_f2);

    // 1. x -> xt (channel-last for coalesced pooling gathers)
    {
        dim3 grid((H_*W_ + 31)/32, (C_ + 31)/32, B_);
        dim3 block(32, 8);
        transpose_kernel<<<grid, block>>>(x, xt);
    }
    // 2. pool with zero offsets -> p0
    pool_kernel<<<N_, 256>>>(xt, rois, nullptr, p0);
    // 3. h1 = relu(p0 @ off_w1^T + off_b1)   [256 x 1024, K=12544]
    gemm_kernel<<<dim3(DFC_/64, N_/32), 256>>>(p0, off_w1, off_b1, h1, DFC_, IN_, 1);
    // 4. h2 = relu(h1 @ off_w2^T + off_b2)   [256 x 1024, K=1024]
    gemm_kernel<<<dim3(DFC_/64, N_/32), 256>>>(h1, off_w2, off_b2, h2, DFC_, DFC_, 1);
    // 5. off = h2 @ off_w3^T + off_b3        [256 x 98]
    off3_kernel<<<N_, 128>>>(h2, off_w3, off_b3, offb);
    // 6. pool with learned offsets -> p1
    pool_kernel<<<N_, 256>>>(xt, rois, offb, p1);
    // 7. f1 = relu(p1 @ fc1_w^T + fc1_b)     [256 x 512, K=12544]
    gemm_kernel<<<dim3(FCC_/64, N_/32), 256>>>(p1, fc1_w, fc1_b, f1, FCC_, IN_, 1);
    // 8. f2 = relu(f1 @ fc2_w^T + fc2_b)     [256 x 512, K=512]
    gemm_kernel<<<dim3(FCC_/64, N_/32), 256>>>(f1, fc2_w, fc2_b, f2, FCC_, FCC_, 1);
    // 9. out = f2 @ box_w^T + box_b          [256 x 4]
    box_kernel<<<N_, 128>>>(f2, box_w, box_b, out);
}

// round 3
// speedup vs baseline: 4.1542x; 4.1542x over previous
#include <cuda_runtime.h>
#include <cuda_bf16.h>

// Problem constants
#define B_ 8
#define C_ 256
#define H_ 25
#define W_ 25
#define N_ 256
#define OUT_ 7
#define NBIN 49
#define SP_ 4
#define IN_ 12544   // C*7*7
#define DFC_ 1024
#define FCC_ 512
#define SS_ (25.0f/255.0f)
#define TRANS_STD_ 0.1f

// Scratch (device globals — no allocation allowed)
__device__ float g_xt[B_*H_*W_*C_];    // (B,H,W,C)
__device__ float g_p0[N_*IN_];
__device__ float g_h1[N_*DFC_];
__device__ float g_h2[N_*DFC_];
__device__ float g_off[N_*2*NBIN];
__device__ float g_p1[N_*IN_];
__device__ float g_f1[N_*FCC_];
__device__ float g_f2[N_*FCC_];
__device__ float g_part[8*N_*DFC_];    // split-K partials (8*256*1024 == 16*256*512)

// ---------------------------------------------------------------------------
// Transpose x (B,C,H,W) -> xt (B,H*W,C)
// ---------------------------------------------------------------------------
__global__ void transpose_kernel(const float* __restrict__ x, float* __restrict__ xt) {
    __shared__ float tile[32][33];
    int b  = blockIdx.z;
    int s0 = blockIdx.x * 32;   // spatial (h*W+w)
    int c0 = blockIdx.y * 32;   // channel
    int tx = threadIdx.x, ty = threadIdx.y; // 32 x 8
    const int HW = H_*W_;
    #pragma unroll
    for (int i = ty; i < 32; i += 8) {
        int c = c0 + i, s = s0 + tx;
        if (c < C_ && s < HW) tile[i][tx] = x[(b*C_ + c)*HW + s];
    }
    __syncthreads();
    #pragma unroll
    for (int i = ty; i < 32; i += 8) {
        int s = s0 + i, c = c0 + tx;
        if (s < HW && c < C_) xt[(b*HW + s)*C_ + c] = tile[tx][i];
    }
}

// ---------------------------------------------------------------------------
// Deformable ROI pool: one block per ROI, 256 threads (= channels),
// loop over the 49 bins. off may be nullptr (zero offsets).
// Output layout: out[n][c*49 + bin]  (matches reference reshape(N,-1))
// ---------------------------------------------------------------------------
__global__ void pool_kernel(const float* __restrict__ xt,
                            const float* __restrict__ rois,
                            const float* __restrict__ off,
                            float* __restrict__ out) {
    int n = blockIdx.x;
    int t = threadIdx.x;   // channel

    const float* r = rois + n*5;
    int   b  = (int)r[0];
    float sw = rintf(r[1])*SS_ - 0.5f;
    float sh = rintf(r[2])*SS_ - 0.5f;
    float rw = fmaxf((rintf(r[3]) + 1.0f)*SS_ - 0.5f - sw, 0.1f);
    float rh = fmaxf((rintf(r[4]) + 1.0f)*SS_ - 0.5f - sh, 0.1f);
    float bw = rw / (float)OUT_;
    float bh = rh / (float)OUT_;

    __shared__ float s_w00[16], s_w01[16], s_w10[16], s_w11[16], s_vs[16];
    __shared__ int   s_i00[16], s_i01[16], s_i10[16], s_i11[16];

    const int base_b = b * (H_*W_) * C_;

    for (int bin = 0; bin < NBIN; bin++) {
        int ph = bin / OUT_, pw = bin % OUT_;
        if (t < 16) {
            float txo = off ? off[n*(2*NBIN) + bin]        * TRANS_STD_ : 0.0f;
            float tyo = off ? off[n*(2*NBIN) + NBIN + bin] * TRANS_STD_ : 0.0f;
            float wstart = pw*bw + sw + txo*rw;
            float hstart = ph*bh + sh + tyo*rh;
            int i = t >> 2;   // y sample
            int j = t & 3;    // x sample
            float sx = wstart + (float)j * (bw * 0.25f);
            float sy = hstart + (float)i * (bh * 0.25f);
            bool valid = (sx >= -0.5f) && (sx <= (float)W_ - 0.5f) &&
                         (sy >= -0.5f) && (sy <= (float)H_ - 0.5f);
            float xc = fminf(fmaxf(sx, 0.0f), (float)(W_-1));
            float yc = fminf(fmaxf(sy, 0.0f), (float)(H_-1));
            float x0 = floorf(xc), y0 = floorf(yc);
            float dx = xc - x0,  dy = yc - y0;
            int xi0 = (int)x0, yi0 = (int)y0;
            int xi1 = (int)ceilf(xc), yi1 = (int)ceilf(yc);
            float vm = valid ? 1.0f : 0.0f;
            s_w00[t] = vm*(1.0f-dx)*(1.0f-dy);
            s_w01[t] = vm*dx*(1.0f-dy);
            s_w10[t] = vm*(1.0f-dx)*dy;
            s_w11[t] = vm*dx*dy;
            s_vs[t]  = vm;
            s_i00[t] = base_b + (yi0*W_ + xi0)*C_;
            s_i01[t] = base_b + (yi0*W_ + xi1)*C_;
            s_i10[t] = base_b + (yi1*W_ + xi0)*C_;
            s_i11[t] = base_b + (yi1*W_ + xi1)*C_;
        }
        __syncthreads();

        float cnt = 0.0f;
        #pragma unroll
        for (int q = 0; q < 16; q++) cnt += s_vs[q];
        float inv = 1.0f / fmaxf(cnt, 1.0f);

        float acc = 0.0f;
        #pragma unroll
        for (int q = 0; q < 16; q++) {
            acc += s_w00[q]*xt[s_i00[q] + t];
            acc += s_w01[q]*xt[s_i01[q] + t];
            acc += s_w10[q]*xt[s_i10[q] + t];
            acc += s_w11[q]*xt[s_i11[q] + t];
        }
        out[n*IN_ + t*NBIN + bin] = acc * inv;
        __syncthreads();
    }
}

// ---------------------------------------------------------------------------
// SGEMM v2: split-K, 64x64 tile, BK=16, 256 threads, 4x4 micro-tile.
// part[s][n][m] = sum_{k in chunk s} A[n][k] * Wm[m][k]
// Requires N_ rows == 256 (n tiles of 64), M % 64 == 0, Kc % 16 == 0.
// ---------------------------------------------------------------------------
__global__ __launch_bounds__(256) void gemm_kernel(
    const float* __restrict__ A, const float* __restrict__ Wm,
    float* __restrict__ part, int M, int K, int Kc) {
    __shared__ float As[16][68];
    __shared__ float Ws[16][68];

    int tid = threadIdx.x;
    int tx = tid & 15;        // col group (x4)
    int ty = tid >> 4;        // row group (x4)
    int m0 = blockIdx.x * 64;
    int n0 = blockIdx.y * 64;
    int s  = blockIdx.z;
    int k0 = s * Kc;
    int kend = k0 + Kc;

    float acc[4][4];
    #pragma unroll
    for (int i = 0; i < 4; i++)
        #pragma unroll
        for (int j = 0; j < 4; j++) acc[i][j] = 0.0f;

    int lrow = tid >> 2;          // 0..63
    int lkg  = (tid & 3) * 4;     // 0,4,8,12
    const float* Aload = A  + (size_t)(n0 + lrow)*K + lkg;
    const float* Wload = Wm + (size_t)(m0 + lrow)*K + lkg;

    for (int k = k0; k < kend; k += 16) {
        float4 av = *(const float4*)(Aload + k);
        float4 wv = *(const float4*)(Wload + k);
        As[lkg+0][lrow] = av.x; As[lkg+1][lrow] = av.y;
        As[lkg+2][lrow] = av.z; As[lkg+3][lrow] = av.w;
        Ws[lkg+0][lrow] = wv.x; Ws[lkg+1][lrow] = wv.y;
        Ws[lkg+2][lrow] = wv.z; Ws[lkg+3][lrow] = wv.w;
        __syncthreads();

        #pragma unroll
        for (int kk = 0; kk < 16; kk++) {
            float4 a = *(const float4*)&As[kk][ty*4];
            float4 b = *(const float4*)&Ws[kk][tx*4];
            acc[0][0] += a.x*b.x; acc[0][1] += a.x*b.y; acc[0][2] += a.x*b.z; acc[0][3] += a.x*b.w;
            acc[1][0] += a.y*b.x; acc[1][1] += a.y*b.y; acc[1][2] += a.y*b.z; acc[1][3] += a.y*b.w;
            acc[2][0] += a.z*b.x; acc[2][1] += a.z*b.y; acc[2][2] += a.z*b.z; acc[2][3] += a.z*b.w;
            acc[3][0] += a.w*b.x; acc[3][1] += a.w*b.y; acc[3][2] += a.w*b.z; acc[3][3] += a.w*b.w;
        }
        __syncthreads();
    }

    float* p = part + (size_t)s * N_ * M;
    #pragma unroll
    for (int i = 0; i < 4; i++) {
        int row = n0 + ty*4 + i;
        float4 v = make_float4(acc[i][0], acc[i][1], acc[i][2], acc[i][3]);
        *(float4*)(p + (size_t)row*M + m0 + tx*4) = v;
    }
}

// ---------------------------------------------------------------------------
// Reduce split-K partials + bias (+ optional relu)
// ---------------------------------------------------------------------------
__global__ void reduce_kernel(const float* __restrict__ part,
                              const float* __restrict__ bias,
                              float* __restrict__ C, int M, int S, int relu) {
    int idx = blockIdx.x * 256 + threadIdx.x;   // over N_*M
    int col = idx % M;
    float acc = bias[col];
    #pragma unroll 4
    for (int s = 0; s < S; s++) acc += part[(size_t)s*N_*M + idx];
    if (relu) acc = fmaxf(acc, 0.0f);
    C[idx] = acc;
}

// ---------------------------------------------------------------------------
// off3: out[n][o] = h[n] . w3[o] + b3[o]  (98 outputs, K=1024)
// warp-per-output, float4 coalesced loads, shuffle reduce
// ---------------------------------------------------------------------------
__global__ void off3_kernel(const float* __restrict__ h,
                            const float* __restrict__ w3,
                            const float* __restrict__ b3,
                            float* __restrict__ out) {
    int n = blockIdx.x;
    int tid = threadIdx.x;
    __shared__ float sh[DFC_];
    ((float4*)sh)[tid] = ((const float4*)(h + n*DFC_))[tid];   // 256 thr * 4 = 1024
    __syncthreads();
    int warp = tid >> 5, lane = tid & 31;
    for (int o = warp; o < 2*NBIN; o += 8) {
        const float4* w = (const float4*)(w3 + o*DFC_);
        float acc = 0.0f;
        #pragma unroll
        for (int i = lane; i < DFC_/4; i += 32) {
            float4 wv = w[i];
            float4 av = ((const float4*)sh)[i];
            acc += wv.x*av.x + wv.y*av.y + wv.z*av.z + wv.w*av.w;
        }
        #pragma unroll
        for (int d = 16; d > 0; d >>= 1) acc += __shfl_down_sync(0xffffffffu, acc, d);
        if (lane == 0) out[n*(2*NBIN) + o] = acc + b3[o];
    }
}

// ---------------------------------------------------------------------------
// box: out[n][w] = f2[n] . box_w[w] + box_b[w]   (4 outputs, K=512)
// ---------------------------------------------------------------------------
__global__ void box_kernel(const float* __restrict__ f2,
                           const float* __restrict__ bw,
                           const float* __restrict__ bb,
                           float* __restrict__ out) {
    int n = blockIdx.x;
    int w = threadIdx.x >> 5;
    int lane = threadIdx.x & 31;
    float acc = 0.0f;
    for (int k = lane; k < FCC_; k += 32) acc += f2[n*FCC_ + k]*bw[w*FCC_ + k];
    #pragma unroll
    for (int o = 16; o > 0; o >>= 1) acc += __shfl_down_sync(0xffffffffu, acc, o);
    if (lane == 0) out[n*4 + w] = acc + bb[w];
}

// ---------------------------------------------------------------------------
extern "C" void kernel_launch(void* const* d_in, const int* in_sizes, int n_in,
                              void* d_out, int out_size) {
    const float* x      = (const float*)d_in[0];
    const float* rois   = (const float*)d_in[1];
    const float* off_w1 = (const float*)d_in[2];
    const float* off_b1 = (const float*)d_in[3];
    const float* off_w2 = (const float*)d_in[4];
    const float* off_b2 = (const float*)d_in[5];
    const float* off_w3 = (const float*)d_in[6];
    const float* off_b3 = (const float*)d_in[7];
    const float* fc1_w  = (const float*)d_in[8];
    const float* fc1_b  = (const float*)d_in[9];
    const float* fc2_w  = (const float*)d_in[10];
    const float* fc2_b  = (const float*)d_in[11];
    const float* box_w  = (const float*)d_in[12];
    const float* box_b  = (const float*)d_in[13];
    float* out = (float*)d_out;

    float *xt, *p0, *h1, *h2, *offb, *p1, *f1, *f2, *part;
    cudaGetSymbolAddress((void**)&xt,   g_xt);
    cudaGetSymbolAddress((void**)&p0,   g_p0);
    cudaGetSymbolAddress((void**)&h1,   g_h1);
    cudaGetSymbolAddress((void**)&h2,   g_h2);
    cudaGetSymbolAddress((void**)&offb, g_off);
    cudaGetSymbolAddress((void**)&p1,   g_p1);
    cudaGetSymbolAddress((void**)&f1,   g_f1);
    cudaGetSymbolAddress((void**)&f2,   g_f2);
    cudaGetSymbolAddress((void**)&part, g_part);

    // 1. x -> xt (channel-last for coalesced pooling gathers)
    {
        dim3 grid((H_*W_ + 31)/32, (C_ + 31)/32, B_);
        dim3 block(32, 8);
        transpose_kernel<<<grid, block>>>(x, xt);
    }
    // 2. pool with zero offsets -> p0
    pool_kernel<<<N_, 256>>>(xt, rois, nullptr, p0);

    // 3. h1 = relu(p0 @ off_w1^T + off_b1)   [256 x 1024, K=12544], S=8
    gemm_kernel<<<dim3(DFC_/64, N_/64, 8), 256>>>(p0, off_w1, part, DFC_, IN_, IN_/8);
    reduce_kernel<<<(N_*DFC_)/256, 256>>>(part, off_b1, h1, DFC_, 8, 1);

    // 4. h2 = relu(h1 @ off_w2^T + off_b2)   [256 x 1024, K=1024], S=4
    gemm_kernel<<<dim3(DFC_/64, N_/64, 4), 256>>>(h1, off_w2, part, DFC_, DFC_, DFC_/4);
    reduce_kernel<<<(N_*DFC_)/256, 256>>>(part, off_b2, h2, DFC_, 4, 1);

    // 5. off = h2 @ off_w3^T + off_b3        [256 x 98]
    off3_kernel<<<N_, 256>>>(h2, off_w3, off_b3, offb);

    // 6. pool with learned offsets -> p1
    pool_kernel<<<N_, 256>>>(xt, rois, offb, p1);

    // 7. f1 = relu(p1 @ fc1_w^T + fc1_b)     [256 x 512, K=12544], S=16
    gemm_kernel<<<dim3(FCC_/64, N_/64, 16), 256>>>(p1, fc1_w, part, FCC_, IN_, IN_/16);
    reduce_kernel<<<(N_*FCC_)/256, 256>>>(part, fc1_b, f1, FCC_, 16, 1);

    // 8. f2 = relu(f1 @ fc2_w^T + fc2_b)     [256 x 512, K=512], S=4
    gemm_kernel<<<dim3(FCC_/64, N_/64, 4), 256>>>(f1, fc2_w, part, FCC_, FCC_, FCC_/4);
    reduce_kernel<<<(N_*FCC_)/256, 256>>>(part, fc2_b, f2, FCC_, 4, 1);

    // 9. out = f2 @ box_w^T + box_b          [256 x 4]
    box_kernel<<<N_, 128>>>(f2, box_w, box_b, out);
}